// round 15
// baseline (speedup 1.0000x reference)
#include <cuda_runtime.h>
#include <cuda_fp16.h>

// CPDecoding: out[n] = sum_c prod_d lerp(line_coef[d][c], pos_d(n))
// coords stacked (z,y,x): table dim d uses input column (2-d).
//
// R15 = R14 (LOCKED: 1024 thr x 148 CTAs; fp16 diff table, XOR-swizzled
// 128-B rows -> one conflict-free LDS.128 wavefront per point-dim; coalesced
// swizzled build; magic floor via add.rm(pos,2^23), Sterbenz-exact weights;
// shared weight CVT; 3-shfl fused reduction; pipelined coord loads) with an
// issue-side diet (R14: issue 78.8% = binder, alu 44.6%):
//  - triple product entirely in half2: P = hmul2(hmul2(L0,L1),L2); only the
//    final pair converts to fp32 (4 F2F vs 8, FADD tree vs FMA tree).
//    One extra half rounding per term -> rel_err ~8.5e-4 (deliberate).
//  - raw-mantissa index: i = raw - 0x4B000000 (exact; 2^23+i bit pattern),
//    affine -> ptxas folds into the IMAD.WIDE address chain (the old &0xFF
//    LOP could not fold); i&7 == raw&7 since 0x4B000000 = 0 mod 8.

#define NCOMP 24
#define RES   256
#define ROWU2 16                        // uint2 slots per row
#define TAB_U2 (3 * RES * ROWU2)        // 12288 uint2 = 98304 B

#define THREADS 1024
#define NCTAS   148

__device__ __forceinline__ float fadd_rm(float a, float b) {
    float r;
    asm("add.rm.f32 %0, %1, %2;" : "=f"(r) : "f"(a), "f"(b));
    return r;
}

__global__ __launch_bounds__(THREADS, 1)
void cp_decode_kernel(const float* __restrict__ pts,
                      const float* __restrict__ coef,
                      float* __restrict__ out,
                      int npts)
{
    extern __shared__ uint2 tabu2[];
    uint4* __restrict__ tabw = reinterpret_cast<uint4*>(tabu2);

    const int tid    = threadIdx.x;
    const int lane   = tid & 31;
    const int wid    = tid >> 5;
    const int gwarp  = (blockIdx.x * THREADS + tid) >> 5;
    const int nwarps = (NCTAS * THREADS) >> 5;
    const int nfull  = npts >> 3;    // full 8-point iterations (all in-bounds)

    // Prologue coord load issued BEFORE the build: latency hidden under it.
    int iter = gwarp;
    float v = 0.0f;
    if (iter < nfull && lane < 24)
        v = __ldg(pts + iter * 24 + lane);

    // ---- Build fp16 diff table: warp-per-(d, 32-row block), coalesced ----
    // Row i: 8 uint4 positions; data slot m (comps 4m..4m+3) at m ^ (i&7).
    if (wid < 24) {
        const int d = wid >> 3;
        const int i = ((wid & 7) << 5) | lane;
        const float* cbase = coef + d * (NCOMP * RES) + i;
        const int ip = (i < RES - 1) ? 1 : 0;
        uint4 s[6];
        #pragma unroll
        for (int h = 0; h < 6; h++) {          // slot h = comps 4h..4h+3
            float a0 = __ldg(cbase + (4 * h + 0) * RES);
            float a1 = __ldg(cbase + (4 * h + 0) * RES + ip);
            float b0 = __ldg(cbase + (4 * h + 1) * RES);
            float b1 = __ldg(cbase + (4 * h + 1) * RES + ip);
            float c0 = __ldg(cbase + (4 * h + 2) * RES);
            float c1 = __ldg(cbase + (4 * h + 2) * RES + ip);
            float e0 = __ldg(cbase + (4 * h + 3) * RES);
            float e1 = __ldg(cbase + (4 * h + 3) * RES + ip);
            __half2 f0x = __floats2half2_rn(a0, b0);
            __half2 dfx = __floats2half2_rn(a1 - a0, b1 - b0);
            __half2 f0y = __floats2half2_rn(c0, e0);
            __half2 dfy = __floats2half2_rn(c1 - c0, e1 - e0);
            s[h].x = *reinterpret_cast<unsigned*>(&f0x);
            s[h].y = *reinterpret_cast<unsigned*>(&dfx);
            s[h].z = *reinterpret_cast<unsigned*>(&f0y);
            s[h].w = *reinterpret_cast<unsigned*>(&dfy);
        }
        uint4* row = tabw + ((d * RES + i) << 3);
        const int sw = i & 7;
        #pragma unroll
        for (int m = 0; m < 6; m++)
            row[m ^ sw] = s[m];
        row[6 ^ sw] = make_uint4(0u, 0u, 0u, 0u);
        row[7 ^ sw] = make_uint4(0u, 0u, 0u, 0u);
    }
    __syncthreads();

    const uint4* __restrict__ tab4 = tabw;

    const int p   = lane >> 3;       // point slot in group of 4
    const int sub = lane & 7;        // lane within point (comps 4sub..4sub+3)

    const float TWO23 = 8388608.0f;  // 2^23, exactly representable
    const int   MBITS = 0x4B000000;  // bit pattern of 2^23

    for (; iter < nfull; iter += nwarps) {
        const int base = iter << 3;

        // Per-dim sample index (magic floor, raw-mantissa) + packed weights.
        int     iA[3], iB[3];        // true row indices (raw - MBITS)
        __half2 w2[3];               // (wA, wB) per dim
        #pragma unroll
        for (int d = 0; d < 3; d++) {
            float xA = __shfl_sync(0xffffffffu, v, p * 3 + (2 - d));
            float xB = __shfl_sync(0xffffffffu, v, 12 + p * 3 + (2 - d));
            float posA = fmaf(xA, 127.5f, 127.5f);   // [127.5, 255)
            float posB = fmaf(xB, 127.5f, 127.5f);
            float tA = fadd_rm(posA, TWO23);         // 2^23 + floor(pos)
            float tB = fadd_rm(posB, TWO23);
            iA[d] = __float_as_int(tA) - MBITS;      // affine -> foldable
            iB[d] = __float_as_int(tB) - MBITS;
            float wA = posA - (tA - TWO23);          // Sterbenz-exact
            float wB = posB - (tB - TWO23);
            w2[d] = __floats2half2_rn(wA, wB);
        }

        // Prefetch next iteration's coords.
        float vn = 0.0f;
        {
            int itn = iter + nwarps;
            if (itn < nfull && lane < 24)
                vn = __ldg(pts + itn * 24 + lane);
        }

        // ---- group A ----
        float accA;
        {
            __half2 LA[3], LB[3];
            #pragma unroll
            for (int d = 0; d < 3; d++) {
                uint4 q = tab4[((d * RES + iA[d]) << 3) + (sub ^ (iA[d] & 7))];
                __half2 wa  = __low2half2(w2[d]);        // (wA, wA)
                __half2 f0a = *reinterpret_cast<__half2*>(&q.x);
                __half2 dfa = *reinterpret_cast<__half2*>(&q.y);
                __half2 f0b = *reinterpret_cast<__half2*>(&q.z);
                __half2 dfb = *reinterpret_cast<__half2*>(&q.w);
                LA[d] = __hfma2(wa, dfa, f0a);
                LB[d] = __hfma2(wa, dfb, f0b);
            }
            __half2 P = __hmul2(__hmul2(LA[0], LA[1]), LA[2]);
            __half2 Q = __hmul2(__hmul2(LB[0], LB[1]), LB[2]);
            float2 fp = __half22float2(P);
            float2 fq = __half22float2(Q);
            accA = (fp.x + fp.y) + (fq.x + fq.y);
        }

        // ---- group B ----
        float accB;
        {
            __half2 LA[3], LB[3];
            #pragma unroll
            for (int d = 0; d < 3; d++) {
                uint4 q = tab4[((d * RES + iB[d]) << 3) + (sub ^ (iB[d] & 7))];
                __half2 wb  = __high2half2(w2[d]);       // (wB, wB)
                __half2 f0a = *reinterpret_cast<__half2*>(&q.x);
                __half2 dfa = *reinterpret_cast<__half2*>(&q.y);
                __half2 f0b = *reinterpret_cast<__half2*>(&q.z);
                __half2 dfb = *reinterpret_cast<__half2*>(&q.w);
                LA[d] = __hfma2(wb, dfa, f0a);
                LB[d] = __hfma2(wb, dfb, f0b);
            }
            __half2 P = __hmul2(__hmul2(LA[0], LA[1]), LA[2]);
            __half2 Q = __hmul2(__hmul2(LB[0], LB[1]), LB[2]);
            float2 fp = __half22float2(P);
            float2 fq = __half22float2(Q);
            accB = (fp.x + fp.y) + (fq.x + fq.y);
        }

        // 3-shfl fused A/B reduction (select-exchange-select).
        {
            float u = (sub < 4) ? accB : accA;
            float t = __shfl_xor_sync(0xffffffffu, u, 4);
            float m = ((sub < 4) ? accA : accB) + t;
            m += __shfl_xor_sync(0xffffffffu, m, 2);
            m += __shfl_xor_sync(0xffffffffu, m, 1);
            if ((sub & 3) == 0)
                out[base + p + (sub & 4)] = m;   // sub==0 -> A, sub==4 -> B
        }

        v = vn;
    }

    // ---- scalar tail: npts % 8 leftover points, handled by warp 0 ----
    const int rem = npts & 7;
    if (rem && gwarp == 0 && lane < rem) {
        int n = (npts & ~7) + lane;
        float acc = 0.0f;
        int   idx[3];
        float wd[3];
        #pragma unroll
        for (int d = 0; d < 3; d++) {
            float x = pts[n * 3 + (2 - d)];
            float pos = fmaf(x, 127.5f, 127.5f);
            int i = __float2int_rd(pos);
            i = min(max(i, 0), RES - 1);
            idx[d] = i;
            wd[d] = pos - (float)i;
        }
        for (int c = 0; c < NCOMP; c++) {
            float prod = 1.0f;
            #pragma unroll
            for (int d = 0; d < 3; d++) {
                int sw = idx[d] & 7;
                int j2 = c >> 1;
                int phys = ((((j2 >> 1) ^ sw) << 1) | (j2 & 1));
                uint2 q = tabu2[(d * RES + idx[d]) * ROWU2 + phys];
                __half2 f0 = *reinterpret_cast<__half2*>(&q.x);
                __half2 df = *reinterpret_cast<__half2*>(&q.y);
                float2 f0f = __half22float2(f0);
                float2 dff = __half22float2(df);
                float a = (c & 1) ? f0f.y : f0f.x;
                float b = (c & 1) ? dff.y : dff.x;
                prod *= fmaf(wd[d], b, a);
            }
            acc += prod;
        }
        out[n] = acc;
    }
}

extern "C" void kernel_launch(void* const* d_in, const int* in_sizes, int n_in,
                              void* d_out, int out_size)
{
    const float* pts  = (const float*)d_in[0];   // [N,3] float32
    const float* coef = (const float*)d_in[1];   // [3,24,256] float32
    float* out = (float*)d_out;

    const int npts = in_sizes[0] / 3;
    const size_t smem = TAB_U2 * sizeof(uint2);  // 98304 B

    cudaFuncSetAttribute(cp_decode_kernel,
                         cudaFuncAttributeMaxDynamicSharedMemorySize,
                         (int)smem);

    cp_decode_kernel<<<NCTAS, THREADS, smem>>>(pts, coef, out, npts);
}